// round 1
// baseline (speedup 1.0000x reference)
#include <cuda_runtime.h>
#include <math.h>

// Problem dims
#define Bsz 16
#define Lsz 1024
#define DMv 512
#define DIv 1024
#define STv 16
#define DCv 4
#define RKv 32
#define ODv 128
#define MTOK (Bsz*Lsz)          // 16384 tokens
#define XPD (RKv + 2*STv)       // 64

// ---------------- scratch (device globals; no runtime allocation) ----------------
__device__ float g_xz  [(size_t)MTOK * 2 * DIv];   // [m, 2048] : xin | z
__device__ float g_xc  [(size_t)MTOK * DIv];       // conv+silu output
__device__ float g_xdbl[(size_t)MTOK * XPD];       // [m, 64] : dt_in | B | C
__device__ float g_dt  [(size_t)MTOK * DIv];       // softplus(dt)
__device__ float g_y   [(size_t)MTOK * DIv];       // gated scan output
__device__ float g_out1[(size_t)MTOK * DMv];       // y @ W_out
__device__ float g_part[256 * Bsz * ODv];          // split-K partials for FC

// ---------------- generic fp32 SGEMM: C[M,N] = A[M,K] @ B[K,N] (row-major) -------
template<int BM, int BN, int BK, int TM, int TN>
__global__ void sgemm_k(const float* __restrict__ A, const float* __restrict__ B,
                        float* __restrict__ C, int M, int N, int K) {
    __shared__ float As[BK][BM];
    __shared__ float Bs[BK][BN];
    constexpr int NT = (BM / TM) * (BN / TN);
    const int tid  = threadIdx.x;
    const int brow = blockIdx.y * BM;
    const int bcol = blockIdx.x * BN;
    const int tcol = (tid % (BN / TN)) * TN;
    const int trow = (tid / (BN / TN)) * TM;

    float acc[TM][TN];
#pragma unroll
    for (int i = 0; i < TM; i++)
#pragma unroll
        for (int j = 0; j < TN; j++) acc[i][j] = 0.f;

    for (int k0 = 0; k0 < K; k0 += BK) {
#pragma unroll
        for (int i = tid; i < BM * BK / 4; i += NT) {
            int r = i / (BK / 4), c = (i % (BK / 4)) * 4;
            float4 v = *(const float4*)&A[(size_t)(brow + r) * K + k0 + c];
            As[c + 0][r] = v.x; As[c + 1][r] = v.y;
            As[c + 2][r] = v.z; As[c + 3][r] = v.w;
        }
#pragma unroll
        for (int i = tid; i < BK * BN / 4; i += NT) {
            int r = i / (BN / 4), c = (i % (BN / 4)) * 4;
            *(float4*)&Bs[r][c] = *(const float4*)&B[(size_t)(k0 + r) * N + bcol + c];
        }
        __syncthreads();
#pragma unroll
        for (int kk = 0; kk < BK; kk++) {
            float ra[TM], rb[TN];
#pragma unroll
            for (int i = 0; i < TM; i++) ra[i] = As[kk][trow + i];
#pragma unroll
            for (int j = 0; j < TN; j++) rb[j] = Bs[kk][tcol + j];
#pragma unroll
            for (int i = 0; i < TM; i++)
#pragma unroll
                for (int j = 0; j < TN; j++)
                    acc[i][j] = fmaf(ra[i], rb[j], acc[i][j]);
        }
        __syncthreads();
    }
#pragma unroll
    for (int i = 0; i < TM; i++)
#pragma unroll
        for (int j = 0; j < TN; j += 4)
            *(float4*)&C[(size_t)(brow + trow + i) * N + bcol + tcol + j] =
                make_float4(acc[i][j], acc[i][j + 1], acc[i][j + 2], acc[i][j + 3]);
}

// ---------------- depthwise causal conv (DC=4) + SiLU ----------------------------
__global__ void conv_silu_k(const float* __restrict__ cw, const float* __restrict__ cb) {
    int idx = blockIdx.x * blockDim.x + threadIdx.x;
    if (idx >= MTOK * DIv) return;
    int d = idx % DIv;
    int m = idx / DIv;          // m = b*L + t
    int t = m % Lsz;
    float acc = cb[d];
#pragma unroll
    for (int j = 0; j < DCv; j++) {
        int tt = t + j - (DCv - 1);
        if (tt >= 0)
            acc = fmaf(g_xz[(size_t)(m + j - (DCv - 1)) * (2 * DIv) + d], cw[d * DCv + j], acc);
    }
    float s = 1.f / (1.f + __expf(-acc));
    g_xc[idx] = acc * s;
}

// ---------------- dt = softplus(xdbl[:, :RK] @ W_dt + b_dt) ----------------------
__device__ __forceinline__ float softplus_f(float x) {
    return (x > 20.f) ? x : log1pf(__expf(x));
}

__global__ void dt_k(const float* __restrict__ Wdt, const float* __restrict__ bdt) {
    int m  = blockIdx.x;            // token
    int d0 = threadIdx.x * 4;       // 256 threads * 4 = 1024 channels
    float4 acc = *(const float4*)&bdt[d0];
    const float* xr = &g_xdbl[(size_t)m * XPD];
#pragma unroll
    for (int k = 0; k < RKv; k++) {
        float xv = xr[k];
        float4 w = *(const float4*)&Wdt[k * DIv + d0];
        acc.x = fmaf(xv, w.x, acc.x);
        acc.y = fmaf(xv, w.y, acc.y);
        acc.z = fmaf(xv, w.z, acc.z);
        acc.w = fmaf(xv, w.w, acc.w);
    }
    float4 o;
    o.x = softplus_f(acc.x); o.y = softplus_f(acc.y);
    o.z = softplus_f(acc.z); o.w = softplus_f(acc.w);
    *(float4*)&g_dt[(size_t)m * DIv + d0] = o;
}

// ---------------- sequential selective scan, fused gate epilogue ------------------
// thread <- (b, d) chain; h[ST] in registers; y = (scan + Dp*u) * silu(z)
__global__ void scan_k(const float* __restrict__ A_log, const float* __restrict__ Dp,
                       float* __restrict__ y) {
    int gid = blockIdx.x * blockDim.x + threadIdx.x;   // 16384
    int b = gid / DIv, d = gid % DIv;
    float A[STv], h[STv];
#pragma unroll
    for (int s = 0; s < STv; s++) {
        A[s] = -__expf(A_log[d * STv + s]);
        h[s] = 0.f;
    }
    float dp = Dp[d];
    for (int t = 0; t < Lsz; t++) {
        size_t m = (size_t)b * Lsz + t;
        float dtv = g_dt[m * DIv + d];
        float u   = g_xc[m * DIv + d];
        float zv  = g_xz[m * 2 * DIv + DIv + d];
        const float4* bc = (const float4*)&g_xdbl[m * XPD + RKv];
        float Bv[STv], Cv[STv];
        *(float4*)&Bv[0]  = bc[0]; *(float4*)&Bv[4]  = bc[1];
        *(float4*)&Bv[8]  = bc[2]; *(float4*)&Bv[12] = bc[3];
        *(float4*)&Cv[0]  = bc[4]; *(float4*)&Cv[4]  = bc[5];
        *(float4*)&Cv[8]  = bc[6]; *(float4*)&Cv[12] = bc[7];
        float dtu = dtv * u;
        float accv = 0.f;
#pragma unroll
        for (int s = 0; s < STv; s++) {
            float dA = __expf(dtv * A[s]);
            h[s] = fmaf(h[s], dA, dtu * Bv[s]);
            accv = fmaf(h[s], Cv[s], accv);
        }
        float yv = fmaf(dp, u, accv);
        float sg = 1.f / (1.f + __expf(-zv));
        y[m * DIv + d] = yv * (zv * sg);
    }
}

// ---------------- final FC: out[16,128] = out1.view(16, L*DM) @ W_fc + b_fc ------
// split-K: 256 chunks of 2048; deterministic two-stage reduction (no float atomics)
__global__ void fc_partial_k(const float* __restrict__ Wfc) {
    __shared__ float sa[Bsz][128];
    const int KTOT = Lsz * DMv;        // 524288
    const int KC   = KTOT / 256;       // 2048
    int k0 = blockIdx.x * KC;
    int n  = threadIdx.x;              // 128
    float acc[Bsz];
#pragma unroll
    for (int m = 0; m < Bsz; m++) acc[m] = 0.f;

    for (int ks = 0; ks < KC; ks += 128) {
        __syncthreads();
#pragma unroll
        for (int m = 0; m < Bsz; m++)
            sa[m][n] = g_out1[(size_t)m * KTOT + k0 + ks + n];
        __syncthreads();
        for (int kk = 0; kk < 128; kk++) {
            float w = Wfc[(size_t)(k0 + ks + kk) * ODv + n];
#pragma unroll
            for (int m = 0; m < Bsz; m++)
                acc[m] = fmaf(sa[m][kk], w, acc[m]);
        }
    }
#pragma unroll
    for (int m = 0; m < Bsz; m++)
        g_part[blockIdx.x * (Bsz * ODv) + m * ODv + n] = acc[m];
}

__global__ void fc_reduce_k(const float* __restrict__ bfc, float* __restrict__ out) {
    int i = blockIdx.x * blockDim.x + threadIdx.x;   // 2048
    if (i >= Bsz * ODv) return;
    int n = i % ODv;
    float acc = bfc[n];
    for (int c = 0; c < 256; c++) acc += g_part[c * (Bsz * ODv) + i];
    out[i] = acc;
}

// ---------------- launch ----------------------------------------------------------
extern "C" void kernel_launch(void* const* d_in, const int* in_sizes, int n_in,
                              void* d_out, int out_size) {
    const float* x       = (const float*)d_in[0];
    const float* W_in    = (const float*)d_in[1];
    const float* conv_w  = (const float*)d_in[2];
    const float* conv_b  = (const float*)d_in[3];
    const float* W_xproj = (const float*)d_in[4];
    const float* W_dt    = (const float*)d_in[5];
    const float* b_dt    = (const float*)d_in[6];
    const float* A_log   = (const float*)d_in[7];
    const float* Dp      = (const float*)d_in[8];
    const float* W_out   = (const float*)d_in[9];
    const float* W_fc    = (const float*)d_in[10];
    const float* b_fc    = (const float*)d_in[11];
    float* out = (float*)d_out;

    float *p_xz, *p_xc, *p_xdbl, *p_y, *p_out1;
    cudaGetSymbolAddress((void**)&p_xz,   g_xz);
    cudaGetSymbolAddress((void**)&p_xc,   g_xc);
    cudaGetSymbolAddress((void**)&p_xdbl, g_xdbl);
    cudaGetSymbolAddress((void**)&p_y,    g_y);
    cudaGetSymbolAddress((void**)&p_out1, g_out1);

    // 1) xz = x @ W_in   [16384,512]x[512,2048]
    sgemm_k<128, 128, 8, 8, 8><<<dim3((2 * DIv) / 128, MTOK / 128), 256>>>(
        x, W_in, p_xz, MTOK, 2 * DIv, DMv);

    // 2) xc = silu(causal depthwise conv(xin))
    conv_silu_k<<<(MTOK * DIv) / 256, 256>>>(conv_w, conv_b);

    // 3) x_dbl = xc @ W_xproj   [16384,1024]x[1024,64]
    sgemm_k<128, 64, 8, 8, 4><<<dim3(1, MTOK / 128), 256>>>(
        p_xc, W_xproj, p_xdbl, MTOK, XPD, DIv);

    // 4) dt = softplus(x_dbl[:, :32] @ W_dt + b_dt)
    dt_k<<<MTOK, 256>>>(W_dt, b_dt);

    // 5) selective scan + gate: y = (scan + Dp*xc) * silu(z)
    scan_k<<<(Bsz * DIv) / 64, 64>>>(A_log, Dp, p_y);

    // 6) out1 = y @ W_out   [16384,1024]x[1024,512]
    sgemm_k<128, 128, 8, 8, 8><<<dim3(DMv / 128, MTOK / 128), 256>>>(
        p_y, W_out, p_out1, MTOK, DMv, DIv);

    // 7) final FC, split-K + deterministic reduce
    fc_partial_k<<<256, 128>>>(W_fc);
    fc_reduce_k<<<(Bsz * ODv + 127) / 128, 128>>>(b_fc, out);
}

// round 2
// speedup vs baseline: 1.4465x; 1.4465x over previous
#include <cuda_runtime.h>
#include <math.h>
#include <stdint.h>

// Problem dims
#define Bsz 16
#define Lsz 1024
#define DMv 512
#define DIv 1024
#define STv 16
#define DCv 4
#define RKv 32
#define ODv 128
#define MTOK (Bsz*Lsz)          // 16384 tokens
#define XPD (RKv + 2*STv)       // 64

// ---------------- scratch (device globals; no runtime allocation) ----------------
__device__ float g_xz  [(size_t)MTOK * 2 * DIv];   // [m, 2048] : xin | z
__device__ float g_xc  [(size_t)MTOK * DIv];       // conv+silu output
__device__ float g_xdbl[(size_t)MTOK * XPD];       // [m, 64] : dt_in | B | C
__device__ float g_dt  [(size_t)MTOK * DIv];       // softplus(dt)
__device__ float g_y   [(size_t)MTOK * DIv];       // gated scan output
__device__ float g_out1[(size_t)MTOK * DMv];       // y @ W_out
__device__ float g_part[256 * Bsz * ODv];          // split-K partials for FC

// =========================== tf32 tensor-core GEMM ================================
// C[M,N] = A[M,K] @ B[K,N], row-major, fp32 in/out, tf32 (rna) compute.
// Block tile 128x128x32; 8 warps, warp tile 64x32 (4x4 mma m16n8k8).

__device__ __forceinline__ uint32_t f2tf32(float x) {
    uint32_t u;
    asm("cvt.rna.tf32.f32 %0, %1;" : "=r"(u) : "f"(x));
    return u;
}

__device__ __forceinline__ void mma_tf32(float* c, const uint32_t* a, const uint32_t* b) {
    asm volatile(
        "mma.sync.aligned.m16n8k8.row.col.f32.tf32.tf32.f32 "
        "{%0,%1,%2,%3},{%4,%5,%6,%7},{%8,%9},{%0,%1,%2,%3};\n"
        : "+f"(c[0]), "+f"(c[1]), "+f"(c[2]), "+f"(c[3])
        : "r"(a[0]), "r"(a[1]), "r"(a[2]), "r"(a[3]), "r"(b[0]), "r"(b[1]));
}

#define BM 128
#define BN 128
#define BKt 32
#define AST 36      // As row stride (pad: bank = 4*row + k, conflict-free frags)
#define BST 136     // Bs row stride (pad: bank = 8*k + n, conflict-free frags)

__global__ __launch_bounds__(256, 2)
void tf32gemm_k(const float* __restrict__ A, const float* __restrict__ B,
                float* __restrict__ C, int M, int N, int K) {
    __shared__ uint32_t As[BM * AST];
    __shared__ uint32_t Bs[BKt * BST];

    const int tid  = threadIdx.x;
    const int lane = tid & 31;
    const int warp = tid >> 5;
    const int wm   = warp >> 2;        // 0..1  -> row offset wm*64
    const int wn   = warp & 3;         // 0..3  -> col offset wn*32
    const int g    = lane >> 2;        // group id 0..7
    const int tq   = lane & 3;         // thread-in-group 0..3
    const int brow = blockIdx.y * BM;
    const int bcol = blockIdx.x * BN;

    float acc[4][4][4];
#pragma unroll
    for (int i = 0; i < 4; i++)
#pragma unroll
        for (int j = 0; j < 4; j++)
#pragma unroll
            for (int r = 0; r < 4; r++) acc[i][j][r] = 0.f;

    for (int k0 = 0; k0 < K; k0 += BKt) {
        // ---- global -> smem (with rna tf32 rounding) ----
#pragma unroll
        for (int i = 0; i < 4; i++) {
            int slot = tid + i * 256;              // 1024 float4 slots
            int row = slot >> 3, kq = (slot & 7) * 4;
            float4 v = *(const float4*)&A[(size_t)(brow + row) * K + k0 + kq];
            uint4 u = make_uint4(f2tf32(v.x), f2tf32(v.y), f2tf32(v.z), f2tf32(v.w));
            *(uint4*)&As[row * AST + kq] = u;
        }
#pragma unroll
        for (int i = 0; i < 4; i++) {
            int slot = tid + i * 256;
            int row = slot >> 5, nq = (slot & 31) * 4;
            float4 v = *(const float4*)&B[(size_t)(k0 + row) * N + bcol + nq];
            uint4 u = make_uint4(f2tf32(v.x), f2tf32(v.y), f2tf32(v.z), f2tf32(v.w));
            *(uint4*)&Bs[row * BST + nq] = u;
        }
        __syncthreads();

        // ---- compute: 4 k-steps of 8 ----
#pragma unroll
        for (int kt = 0; kt < 4; kt++) {
            const int ks = kt * 8;
            uint32_t af[4][4], bf[4][2];
#pragma unroll
            for (int mm = 0; mm < 4; mm++) {
                int r0 = wm * 64 + mm * 16 + g;
                af[mm][0] = As[r0 * AST + ks + tq];
                af[mm][1] = As[(r0 + 8) * AST + ks + tq];
                af[mm][2] = As[r0 * AST + ks + tq + 4];
                af[mm][3] = As[(r0 + 8) * AST + ks + tq + 4];
            }
#pragma unroll
            for (int nn = 0; nn < 4; nn++) {
                int c0 = wn * 32 + nn * 8 + g;
                bf[nn][0] = Bs[(ks + tq) * BST + c0];
                bf[nn][1] = Bs[(ks + tq + 4) * BST + c0];
            }
#pragma unroll
            for (int mm = 0; mm < 4; mm++)
#pragma unroll
                for (int nn = 0; nn < 4; nn++)
                    mma_tf32(acc[mm][nn], af[mm], bf[nn]);
        }
        __syncthreads();
    }

    // ---- epilogue ----
#pragma unroll
    for (int mm = 0; mm < 4; mm++) {
#pragma unroll
        for (int nn = 0; nn < 4; nn++) {
            int r = brow + wm * 64 + mm * 16 + g;
            int c = bcol + wn * 32 + nn * 8 + tq * 2;
            *(float2*)&C[(size_t)r * N + c]       = make_float2(acc[mm][nn][0], acc[mm][nn][1]);
            *(float2*)&C[(size_t)(r + 8) * N + c] = make_float2(acc[mm][nn][2], acc[mm][nn][3]);
        }
    }
}

// ---------------- generic fp32 SGEMM (kept for the skinny xproj GEMM) ------------
template<int TBM, int TBN, int TBK, int TM, int TN>
__global__ void sgemm_k(const float* __restrict__ A, const float* __restrict__ B,
                        float* __restrict__ C, int M, int N, int K) {
    __shared__ float As2[TBK][TBM];
    __shared__ float Bs2[TBK][TBN];
    constexpr int NT = (TBM / TM) * (TBN / TN);
    const int tid  = threadIdx.x;
    const int brow = blockIdx.y * TBM;
    const int bcol = blockIdx.x * TBN;
    const int tcol = (tid % (TBN / TN)) * TN;
    const int trow = (tid / (TBN / TN)) * TM;

    float acc[TM][TN];
#pragma unroll
    for (int i = 0; i < TM; i++)
#pragma unroll
        for (int j = 0; j < TN; j++) acc[i][j] = 0.f;

    for (int k0 = 0; k0 < K; k0 += TBK) {
#pragma unroll
        for (int i = tid; i < TBM * TBK / 4; i += NT) {
            int r = i / (TBK / 4), c = (i % (TBK / 4)) * 4;
            float4 v = *(const float4*)&A[(size_t)(brow + r) * K + k0 + c];
            As2[c + 0][r] = v.x; As2[c + 1][r] = v.y;
            As2[c + 2][r] = v.z; As2[c + 3][r] = v.w;
        }
#pragma unroll
        for (int i = tid; i < TBK * TBN / 4; i += NT) {
            int r = i / (TBN / 4), c = (i % (TBN / 4)) * 4;
            *(float4*)&Bs2[r][c] = *(const float4*)&B[(size_t)(k0 + r) * N + bcol + c];
        }
        __syncthreads();
#pragma unroll
        for (int kk = 0; kk < TBK; kk++) {
            float ra[TM], rb[TN];
#pragma unroll
            for (int i = 0; i < TM; i++) ra[i] = As2[kk][trow + i];
#pragma unroll
            for (int j = 0; j < TN; j++) rb[j] = Bs2[kk][tcol + j];
#pragma unroll
            for (int i = 0; i < TM; i++)
#pragma unroll
                for (int j = 0; j < TN; j++)
                    acc[i][j] = fmaf(ra[i], rb[j], acc[i][j]);
        }
        __syncthreads();
    }
#pragma unroll
    for (int i = 0; i < TM; i++)
#pragma unroll
        for (int j = 0; j < TN; j += 4)
            *(float4*)&C[(size_t)(brow + trow + i) * N + bcol + tcol + j] =
                make_float4(acc[i][j], acc[i][j + 1], acc[i][j + 2], acc[i][j + 3]);
}

// ---------------- depthwise causal conv (DC=4) + SiLU ----------------------------
__global__ void conv_silu_k(const float* __restrict__ cw, const float* __restrict__ cb) {
    int idx = blockIdx.x * blockDim.x + threadIdx.x;
    if (idx >= MTOK * DIv) return;
    int d = idx % DIv;
    int m = idx / DIv;          // m = b*L + t
    int t = m % Lsz;
    float acc = cb[d];
#pragma unroll
    for (int j = 0; j < DCv; j++) {
        int tt = t + j - (DCv - 1);
        if (tt >= 0)
            acc = fmaf(g_xz[(size_t)(m + j - (DCv - 1)) * (2 * DIv) + d], cw[d * DCv + j], acc);
    }
    float s = 1.f / (1.f + __expf(-acc));
    g_xc[idx] = acc * s;
}

// ---------------- dt = softplus(xdbl[:, :RK] @ W_dt + b_dt), smem-tiled ----------
__device__ __forceinline__ float softplus_f(float x) {
    return (x > 20.f) ? x : log1pf(__expf(x));
}

// grid (DIv/256, MTOK/32), block 256. Each thread: 4 tokens x 8 strided channels.
__global__ void dt_k(const float* __restrict__ Wdt, const float* __restrict__ bdt) {
    __shared__ float sW[RKv * 256];       // [k][ch], 32KB
    __shared__ float sx[32 * RKv];        // [tok][k], 4KB
    const int tid = threadIdx.x;
    const int ch0 = blockIdx.x * 256;
    const int m0  = blockIdx.y * 32;
    const int cg  = tid & 31;             // lane -> channel base
    const int tg  = tid >> 5;             // warp -> token group (4 tokens)

#pragma unroll
    for (int j = 0; j < 8; j++) {
        int slot = tid + j * 256;                 // 2048 float4 slots
        int k = slot >> 6, c4 = (slot & 63) * 4;
        *(float4*)&sW[k * 256 + c4] = *(const float4*)&Wdt[(size_t)k * DIv + ch0 + c4];
    }
    {
        int tok = tid >> 3, k4 = (tid & 7) * 4;   // 256 float4 slots
        *(float4*)&sx[tok * RKv + k4] = *(const float4*)&g_xdbl[(size_t)(m0 + tok) * XPD + k4];
    }
    __syncthreads();

    float acc[4][8];
#pragma unroll
    for (int i = 0; i < 4; i++)
#pragma unroll
        for (int j = 0; j < 8; j++) acc[i][j] = bdt[ch0 + cg + 32 * j];

    for (int k = 0; k < RKv; k++) {
        float wv[8];
#pragma unroll
        for (int j = 0; j < 8; j++) wv[j] = sW[k * 256 + cg + 32 * j];
#pragma unroll
        for (int i = 0; i < 4; i++) {
            float xv = sx[(tg * 4 + i) * RKv + k];
#pragma unroll
            for (int j = 0; j < 8; j++) acc[i][j] = fmaf(xv, wv[j], acc[i][j]);
        }
    }
#pragma unroll
    for (int i = 0; i < 4; i++)
#pragma unroll
        for (int j = 0; j < 8; j++)
            g_dt[(size_t)(m0 + tg * 4 + i) * DIv + ch0 + cg + 32 * j] = softplus_f(acc[i][j]);
}

// ---------------- sequential selective scan, fused gate epilogue ------------------
__global__ void scan_k(const float* __restrict__ A_log, const float* __restrict__ Dp,
                       float* __restrict__ y) {
    int gid = blockIdx.x * blockDim.x + threadIdx.x;   // 16384
    int b = gid / DIv, d = gid % DIv;
    float A[STv], h[STv];
#pragma unroll
    for (int s = 0; s < STv; s++) {
        A[s] = -__expf(A_log[d * STv + s]);
        h[s] = 0.f;
    }
    float dp = Dp[d];
    for (int t = 0; t < Lsz; t++) {
        size_t m = (size_t)b * Lsz + t;
        float dtv = g_dt[m * DIv + d];
        float u   = g_xc[m * DIv + d];
        float zv  = g_xz[m * 2 * DIv + DIv + d];
        const float4* bc = (const float4*)&g_xdbl[m * XPD + RKv];
        float Bv[STv], Cv[STv];
        *(float4*)&Bv[0]  = bc[0]; *(float4*)&Bv[4]  = bc[1];
        *(float4*)&Bv[8]  = bc[2]; *(float4*)&Bv[12] = bc[3];
        *(float4*)&Cv[0]  = bc[4]; *(float4*)&Cv[4]  = bc[5];
        *(float4*)&Cv[8]  = bc[6]; *(float4*)&Cv[12] = bc[7];
        float dtu = dtv * u;
        float accv = 0.f;
#pragma unroll
        for (int s = 0; s < STv; s++) {
            float dA = __expf(dtv * A[s]);
            h[s] = fmaf(h[s], dA, dtu * Bv[s]);
            accv = fmaf(h[s], Cv[s], accv);
        }
        float yv = fmaf(dp, u, accv);
        float sg = 1.f / (1.f + __expf(-zv));
        y[m * DIv + d] = yv * (zv * sg);
    }
}

// ---------------- final FC: out[16,128] = out1.view(16, L*DM) @ W_fc + b_fc ------
__global__ void fc_partial_k(const float* __restrict__ Wfc) {
    __shared__ float sa[Bsz][128];
    const int KTOT = Lsz * DMv;        // 524288
    const int KC   = KTOT / 256;       // 2048
    int k0 = blockIdx.x * KC;
    int n  = threadIdx.x;              // 128
    float acc[Bsz];
#pragma unroll
    for (int m = 0; m < Bsz; m++) acc[m] = 0.f;

    for (int ks = 0; ks < KC; ks += 128) {
        __syncthreads();
#pragma unroll
        for (int m = 0; m < Bsz; m++)
            sa[m][n] = g_out1[(size_t)m * KTOT + k0 + ks + n];
        __syncthreads();
        for (int kk = 0; kk < 128; kk++) {
            float w = Wfc[(size_t)(k0 + ks + kk) * ODv + n];
#pragma unroll
            for (int m = 0; m < Bsz; m++)
                acc[m] = fmaf(sa[m][kk], w, acc[m]);
        }
    }
#pragma unroll
    for (int m = 0; m < Bsz; m++)
        g_part[blockIdx.x * (Bsz * ODv) + m * ODv + n] = acc[m];
}

__global__ void fc_reduce_k(const float* __restrict__ bfc, float* __restrict__ out) {
    int i = blockIdx.x * blockDim.x + threadIdx.x;   // 2048
    if (i >= Bsz * ODv) return;
    int n = i % ODv;
    float acc = bfc[n];
    for (int c = 0; c < 256; c++) acc += g_part[c * (Bsz * ODv) + i];
    out[i] = acc;
}

// ---------------- launch ----------------------------------------------------------
extern "C" void kernel_launch(void* const* d_in, const int* in_sizes, int n_in,
                              void* d_out, int out_size) {
    const float* x       = (const float*)d_in[0];
    const float* W_in    = (const float*)d_in[1];
    const float* conv_w  = (const float*)d_in[2];
    const float* conv_b  = (const float*)d_in[3];
    const float* W_xproj = (const float*)d_in[4];
    const float* W_dt    = (const float*)d_in[5];
    const float* b_dt    = (const float*)d_in[6];
    const float* A_log   = (const float*)d_in[7];
    const float* Dp      = (const float*)d_in[8];
    const float* W_out   = (const float*)d_in[9];
    const float* W_fc    = (const float*)d_in[10];
    const float* b_fc    = (const float*)d_in[11];
    float* out = (float*)d_out;

    float *p_xz, *p_xc, *p_xdbl, *p_y, *p_out1;
    cudaGetSymbolAddress((void**)&p_xz,   g_xz);
    cudaGetSymbolAddress((void**)&p_xc,   g_xc);
    cudaGetSymbolAddress((void**)&p_xdbl, g_xdbl);
    cudaGetSymbolAddress((void**)&p_y,    g_y);
    cudaGetSymbolAddress((void**)&p_out1, g_out1);

    // 1) xz = x @ W_in   [16384,512]x[512,2048]  (tf32 tensor)
    tf32gemm_k<<<dim3((2 * DIv) / BN, MTOK / BM), 256>>>(x, W_in, p_xz, MTOK, 2 * DIv, DMv);

    // 2) xc = silu(causal depthwise conv(xin))
    conv_silu_k<<<(MTOK * DIv) / 256, 256>>>(conv_w, conv_b);

    // 3) x_dbl = xc @ W_xproj   [16384,1024]x[1024,64]  (fp32)
    sgemm_k<128, 64, 8, 8, 4><<<dim3(1, MTOK / 128), 256>>>(p_xc, W_xproj, p_xdbl, MTOK, XPD, DIv);

    // 4) dt = softplus(x_dbl[:, :32] @ W_dt + b_dt)
    dt_k<<<dim3(DIv / 256, MTOK / 32), 256>>>(W_dt, b_dt);

    // 5) selective scan + gate: y = (scan + Dp*xc) * silu(z)
    scan_k<<<(Bsz * DIv) / 64, 64>>>(A_log, Dp, p_y);

    // 6) out1 = y @ W_out   [16384,1024]x[1024,512]  (tf32 tensor)
    tf32gemm_k<<<dim3(DMv / BN, MTOK / BM), 256>>>(p_y, W_out, p_out1, MTOK, DMv, DIv);

    // 7) final FC, split-K + deterministic reduce
    fc_partial_k<<<256, 128>>>(W_fc);
    fc_reduce_k<<<(Bsz * ODv + 127) / 128, 128>>>(b_fc, out);
}